// round 3
// baseline (speedup 1.0000x reference)
#include <cuda_runtime.h>
#include <cstdint>

#define Bb   2
#define Nn   2048
#define Cc   512
#define Hh   8
#define HD   64
#define BH   16
#define KTOP 1024
#define SCALEF 0.125f

typedef unsigned long long ull;

// ---------------- packed fp32x2 helpers (IEEE fp32 per lane, bit-exact) -----
__device__ __forceinline__ ull pack2(float lo, float hi) {
    ull r; asm("mov.b64 %0,{%1,%2};" : "=l"(r) : "f"(lo), "f"(hi)); return r;
}
__device__ __forceinline__ void ffma2(ull& d, ull a, ull b) {
    asm("fma.rn.f32x2 %0,%1,%2,%3;" : "=l"(d) : "l"(a), "l"(b), "l"(d));
}
__device__ __forceinline__ float2 unpack2(ull v) {
    float2 f; asm("mov.b64 {%0,%1},%2;" : "=f"(f.x), "=f"(f.y) : "l"(v)); return f;
}

// ---------------- scratch ----------------
__device__ float g_Qh[BH * Nn * HD];
__device__ float g_Kh[BH * Nn * HD];
__device__ float g_Vh[BH * Nn * HD];
__device__ float g_attn[(size_t)BH * Nn * Nn];
__device__ float g_attnT[(size_t)BH * Nn * Nn];
__device__ float g_rth[BH * Nn];
__device__ float g_cth[BH * Nn];
__device__ float g_rmax[BH * Nn];
__device__ float g_O[BH * Nn * HD];

#define AS_S 132   // K-major A row stride (16B aligned)
#define BS_S 68    // K-major B row stride (16B aligned)

// ---------------------------------------------------------------------------
// Kernel 1: projections  out = X @ W^T  scattered to [B,H,N,HD]
// tile 128x64, 256 threads, 4x8 per thread (f32x2 pairs along j), BK=32
// ---------------------------------------------------------------------------
__global__ __launch_bounds__(256) void proj_kernel(const float* __restrict__ X,
                                                   const float* __restrict__ W,
                                                   int which) {
    __shared__ float AsT[32][AS_S];   // [kk][m]
    __shared__ float BsT[32][BS_S];   // [kk][n]
    int tid = threadIdx.x;
    int tx = tid & 7, ty = tid >> 3;
    int m0 = blockIdx.y * 128, n0 = blockIdx.x * 64;
    ull acc2[4][4] = {};
    for (int k0 = 0; k0 < Cc; k0 += 32) {
#pragma unroll
        for (int l = tid; l < 1024; l += 256) {          // A 128x32, transpose-store
            int m = l >> 3, c = (l & 7) * 4;
            float4 v = *(const float4*)&X[(size_t)(m0 + m) * Cc + k0 + c];
            AsT[c + 0][m] = v.x; AsT[c + 1][m] = v.y;
            AsT[c + 2][m] = v.z; AsT[c + 3][m] = v.w;
        }
#pragma unroll
        for (int l = tid; l < 512; l += 256) {           // B 64x32
            int n = l >> 3, c = (l & 7) * 4;
            float4 v = *(const float4*)&W[(size_t)(n0 + n) * Cc + k0 + c];
            BsT[c + 0][n] = v.x; BsT[c + 1][n] = v.y;
            BsT[c + 2][n] = v.z; BsT[c + 3][n] = v.w;
        }
        __syncthreads();
#pragma unroll
        for (int kk = 0; kk < 32; kk++) {
            float4 av = *(const float4*)&AsT[kk][4 * ty];
            ull aB[4] = {pack2(av.x, av.x), pack2(av.y, av.y),
                         pack2(av.z, av.z), pack2(av.w, av.w)};
            ulonglong2 bb0 = *(const ulonglong2*)&BsT[kk][8 * tx];
            ulonglong2 bb1 = *(const ulonglong2*)&BsT[kk][8 * tx + 4];
            ull b2[4] = {bb0.x, bb0.y, bb1.x, bb1.y};
#pragma unroll
            for (int i = 0; i < 4; i++)
#pragma unroll
                for (int j = 0; j < 4; j++) ffma2(acc2[i][j], aB[i], b2[j]);
        }
        __syncthreads();
    }
    float* out = (which == 0) ? g_Qh : ((which == 1) ? g_Kh : g_Vh);
#pragma unroll
    for (int i = 0; i < 4; i++) {
        int m = m0 + 4 * ty + i;
        int bb = m >> 11, nl = m & (Nn - 1);
#pragma unroll
        for (int j = 0; j < 4; j++) {
            float2 u = unpack2(acc2[i][j]);
            int n = n0 + 8 * tx + 2 * j;
            int h = n >> 6, d = n & 63;
            float* dst = &out[(((size_t)(bb * Hh + h)) * Nn + nl) * HD + d];
            dst[0] = u.x; dst[1] = u.y;      // d,d+1 same head (HD=64, pairs aligned)
        }
    }
}

// ---------------------------------------------------------------------------
// Kernel 2: attn = scale * Q K^T, plus transposed copy.
// tile 128(i) x 64(j), 256 threads, 4x8 per thread, BK=32 (K=64)
// ---------------------------------------------------------------------------
__global__ __launch_bounds__(256) void qk_kernel() {
    __shared__ float sm[64 * 129];                 // 33KB, reused
    float (*AsT)[AS_S] = (float(*)[AS_S])sm;       // 32x132
    float (*BsT)[BS_S] = (float(*)[BS_S])(sm + 32 * AS_S);
    float (*Ts)[129]   = (float(*)[129])sm;        // 64x129 (after MMA)
    int tid = threadIdx.x;
    int tx = tid & 7, ty = tid >> 3;
    int bh = blockIdx.z;
    int i0 = blockIdx.y * 128, j0 = blockIdx.x * 64;
    const float* Q = g_Qh + (size_t)bh * Nn * HD;
    const float* K = g_Kh + (size_t)bh * Nn * HD;
    ull acc2[4][4] = {};
#pragma unroll
    for (int k0 = 0; k0 < HD; k0 += 32) {
#pragma unroll
        for (int l = tid; l < 1024; l += 256) {
            int m = l >> 3, c = (l & 7) * 4;
            float4 v = *(const float4*)&Q[(size_t)(i0 + m) * HD + k0 + c];
            AsT[c + 0][m] = v.x; AsT[c + 1][m] = v.y;
            AsT[c + 2][m] = v.z; AsT[c + 3][m] = v.w;
        }
#pragma unroll
        for (int l = tid; l < 512; l += 256) {
            int n = l >> 3, c = (l & 7) * 4;
            float4 v = *(const float4*)&K[(size_t)(j0 + n) * HD + k0 + c];
            BsT[c + 0][n] = v.x; BsT[c + 1][n] = v.y;
            BsT[c + 2][n] = v.z; BsT[c + 3][n] = v.w;
        }
        __syncthreads();
#pragma unroll
        for (int kk = 0; kk < 32; kk++) {
            float4 av = *(const float4*)&AsT[kk][4 * ty];
            ull aB[4] = {pack2(av.x, av.x), pack2(av.y, av.y),
                         pack2(av.z, av.z), pack2(av.w, av.w)};
            ulonglong2 bb0 = *(const ulonglong2*)&BsT[kk][8 * tx];
            ulonglong2 bb1 = *(const ulonglong2*)&BsT[kk][8 * tx + 4];
            ull b2[4] = {bb0.x, bb0.y, bb1.x, bb1.y};
#pragma unroll
            for (int i = 0; i < 4; i++)
#pragma unroll
                for (int j = 0; j < 4; j++) ffma2(acc2[i][j], aB[i], b2[j]);
        }
        __syncthreads();
    }
    // scale, store attn, stage transpose
    float* attn = g_attn + ((size_t)bh * Nn + i0) * Nn + j0;
    float r[4][8];
#pragma unroll
    for (int i = 0; i < 4; i++) {
#pragma unroll
        for (int j = 0; j < 4; j++) {
            float2 u = unpack2(acc2[i][j]);
            r[i][2 * j] = u.x * SCALEF; r[i][2 * j + 1] = u.y * SCALEF;
        }
        float4 v0 = make_float4(r[i][0], r[i][1], r[i][2], r[i][3]);
        float4 v1 = make_float4(r[i][4], r[i][5], r[i][6], r[i][7]);
        *(float4*)&attn[(size_t)(4 * ty + i) * Nn + 8 * tx] = v0;
        *(float4*)&attn[(size_t)(4 * ty + i) * Nn + 8 * tx + 4] = v1;
    }
#pragma unroll
    for (int i = 0; i < 4; i++)
#pragma unroll
        for (int j = 0; j < 8; j++) Ts[8 * tx + j][4 * ty + i] = r[i][j];
    __syncthreads();
    float* attnT = g_attnT + ((size_t)bh * Nn + j0) * Nn + i0;
#pragma unroll 4
    for (int l = tid; l < 64 * 128; l += 256) {
        int jl = l >> 7, il = l & 127;
        attnT[(size_t)jl * Nn + il] = Ts[jl][il];
    }
}

// ---------------------------------------------------------------------------
// Kernel 3: exact K_TOP-th largest per row (MSB-first 8-bit radix select).
// grid (BH*N, 2), block 256.  (unchanged from R2 — passed)
// ---------------------------------------------------------------------------
__global__ __launch_bounds__(256) void select_kernel() {
    __shared__ unsigned hist[4][256];
    __shared__ unsigned S[257];
    __shared__ unsigned s_sel, s_maxu;
    int tid = threadIdx.x;
    size_t row = blockIdx.x;
    int dir = blockIdx.y;
    const float* src = (dir ? g_attnT : g_attn) + row * Nn;

    unsigned u[8], lmax = 0u;
#pragma unroll
    for (int r = 0; r < 8; r++) {
        unsigned b = __float_as_uint(src[tid + 256 * r]);
        u[r] = b ^ ((unsigned)((int)b >> 31) | 0x80000000u);
        lmax = lmax > u[r] ? lmax : u[r];
    }
    if (tid == 0) s_maxu = 0u;

    unsigned prefix = 0u;
    int krem = KTOP;
    int hb = tid >> 6;
#pragma unroll
    for (int pass = 0; pass < 4; pass++) {
        int shift = 24 - 8 * pass;
        hist[0][tid] = 0u; hist[1][tid] = 0u; hist[2][tid] = 0u; hist[3][tid] = 0u;
        __syncthreads();
        if (pass == 0) atomicMax(&s_maxu, lmax);
        unsigned himask = (pass == 0) ? 0u : (0xFFFFFFFFu << (shift + 8));
#pragma unroll
        for (int r = 0; r < 8; r++)
            if ((u[r] & himask) == prefix)
                atomicAdd(&hist[hb][(u[r] >> shift) & 255u], 1u);
        __syncthreads();
        unsigned h = hist[0][tid] + hist[1][tid] + hist[2][tid] + hist[3][tid];
        hist[0][tid] = h;
        __syncthreads();
        if (tid < 32) {
            int base = tid * 8;
            unsigned c[8], loc[8];
#pragma unroll
            for (int j = 0; j < 8; j++) c[j] = hist[0][base + j];
            loc[7] = c[7];
#pragma unroll
            for (int j = 6; j >= 0; j--) loc[j] = c[j] + loc[j + 1];
            unsigned T = loc[0], incl = T;
#pragma unroll
            for (int off = 1; off < 32; off <<= 1) {
                unsigned v = __shfl_down_sync(0xFFFFFFFFu, incl, off);
                if (tid + off < 32) incl += v;
            }
            unsigned excl = incl - T;
#pragma unroll
            for (int j = 0; j < 8; j++) S[base + j] = excl + loc[j];
            if (tid == 0) S[256] = 0u;
        }
        __syncthreads();
        unsigned St = S[tid], St1 = S[tid + 1];
        if ((int)St >= krem && (int)St1 < krem) s_sel = (unsigned)tid;
        __syncthreads();
        unsigned sel = s_sel;
        krem -= (int)S[sel + 1];
        prefix |= sel << shift;
        __syncthreads();
    }
    if (tid == 0) {
        unsigned b = (prefix & 0x80000000u) ? (prefix ^ 0x80000000u) : ~prefix;
        float thr = __uint_as_float(b);
        if (dir) {
            g_cth[row] = thr;
        } else {
            g_rth[row] = thr;
            unsigned um = s_maxu;
            unsigned bm = (um & 0x80000000u) ? (um ^ 0x80000000u) : ~um;
            g_rmax[row] = __uint_as_float(bm);
        }
    }
}

// ---------------------------------------------------------------------------
// Kernel 4: fused masked softmax + P@V.  tile 128 rows x 64 HD, 256 threads,
// 4x8 per thread, K chunks of 32.  grid (N/128, BH).
// ---------------------------------------------------------------------------
__global__ __launch_bounds__(256) void spv_kernel() {
    __shared__ float PsT[32][AS_S];   // [kk][row]
    __shared__ float Vs[32][BS_S];    // [kk][d]
    __shared__ float s_rth[128], s_mx[128], s_cth[32];
    int tid = threadIdx.x;
    int tx = tid & 7, ty = tid >> 3;
    int bh = blockIdx.y;
    int i0 = blockIdx.x * 128;
    const float* V = g_Vh + (size_t)bh * Nn * HD;
    const float* A = g_attn + ((size_t)bh * Nn + i0) * Nn;
    if (tid < 128) {
        s_rth[tid] = g_rth[bh * Nn + i0 + tid];
        s_mx[tid]  = g_rmax[bh * Nn + i0 + tid];
    }
    __syncthreads();
    float rthr[4], mr[4], dloc[4];
#pragma unroll
    for (int i = 0; i < 4; i++) {
        rthr[i] = s_rth[4 * ty + i];
        mr[i]   = s_mx[4 * ty + i];
        dloc[i] = 0.f;
    }
    ull acc2[4][4] = {};

    for (int j0 = 0; j0 < Nn; j0 += 32) {
        float4 araw[4];
#pragma unroll
        for (int i = 0; i < 4; i++)
            araw[i] = *(const float4*)&A[(size_t)(4 * ty + i) * Nn + j0 + 4 * tx];
        __syncthreads();               // prev chunk MMA done (PsT/Vs free)
        if (tid < 32) s_cth[tid] = g_cth[bh * Nn + j0 + tid];
#pragma unroll
        for (int l = tid; l < 512; l += 256) {   // V chunk 32x64
            int jl = l >> 4, d = (l & 15) * 4;
            *(float4*)&Vs[jl][d] = *(const float4*)&V[(size_t)(j0 + jl) * HD + d];
        }
        __syncthreads();               // cth + Vs visible
#pragma unroll
        for (int uu = 0; uu < 4; uu++) {
            int col = 4 * tx + uu;
            float cthv = s_cth[col];
            float pv[4];
#pragma unroll
            for (int i = 0; i < 4; i++) {
                float a = (uu == 0) ? araw[i].x : (uu == 1) ? araw[i].y
                        : (uu == 2) ? araw[i].z : araw[i].w;
                float thr = fminf(rthr[i], cthv);
                float p = (a >= thr) ? __expf(a - mr[i]) : 0.f;
                dloc[i] += p;
                pv[i] = p;
            }
            *(float4*)&PsT[col][4 * ty] = make_float4(pv[0], pv[1], pv[2], pv[3]);
        }
        __syncthreads();               // PsT complete
#pragma unroll
        for (int kk = 0; kk < 32; kk++) {
            float4 av = *(const float4*)&PsT[kk][4 * ty];
            ull aB[4] = {pack2(av.x, av.x), pack2(av.y, av.y),
                         pack2(av.z, av.z), pack2(av.w, av.w)};
            ulonglong2 bb0 = *(const ulonglong2*)&Vs[kk][8 * tx];
            ulonglong2 bb1 = *(const ulonglong2*)&Vs[kk][8 * tx + 4];
            ull b2[4] = {bb0.x, bb0.y, bb1.x, bb1.y};
#pragma unroll
            for (int i = 0; i < 4; i++)
#pragma unroll
                for (int j = 0; j < 4; j++) ffma2(acc2[i][j], aB[i], b2[j]);
        }
    }
    // deterministic denominator: sum over the 8 tx-lanes sharing each row group
#pragma unroll
    for (int i = 0; i < 4; i++) {
        dloc[i] += __shfl_xor_sync(0xFFFFFFFFu, dloc[i], 1);
        dloc[i] += __shfl_xor_sync(0xFFFFFFFFu, dloc[i], 2);
        dloc[i] += __shfl_xor_sync(0xFFFFFFFFu, dloc[i], 4);
    }
#pragma unroll
    for (int i = 0; i < 4; i++) {
        float inv = 1.f / dloc[i];
        float o[8];
#pragma unroll
        for (int j = 0; j < 4; j++) {
            float2 u = unpack2(acc2[i][j]);
            o[2 * j] = u.x * inv; o[2 * j + 1] = u.y * inv;
        }
        float* dst = &g_O[((size_t)bh * Nn + i0 + 4 * ty + i) * HD + 8 * tx];
        *(float4*)dst = make_float4(o[0], o[1], o[2], o[3]);
        *(float4*)(dst + 4) = make_float4(o[4], o[5], o[6], o[7]);
    }
}

// ---------------------------------------------------------------------------
// Kernel 5: output projection  out = concat_heads(O) @ Wp^T + bp
// tile 128x64, 256 threads, 4x8
// ---------------------------------------------------------------------------
__global__ __launch_bounds__(256) void outproj_kernel(const float* __restrict__ Wp,
                                                      const float* __restrict__ bp,
                                                      float* __restrict__ out) {
    __shared__ float AsT[32][AS_S];
    __shared__ float BsT[32][BS_S];
    int tid = threadIdx.x;
    int tx = tid & 7, ty = tid >> 3;
    int m0 = blockIdx.y * 128, n0 = blockIdx.x * 64;
    ull acc2[4][4] = {};
    for (int k0 = 0; k0 < Cc; k0 += 32) {
        int h = k0 >> 6;
#pragma unroll
        for (int l = tid; l < 1024; l += 256) {
            int m = l >> 3, c = (l & 7) * 4;
            int mg = m0 + m;
            int bb = mg >> 11, nl = mg & (Nn - 1);
            int d = (k0 + c) & 63;
            float4 v = *(const float4*)&g_O[(((size_t)(bb * Hh + h)) * Nn + nl) * HD + d];
            AsT[c + 0][m] = v.x; AsT[c + 1][m] = v.y;
            AsT[c + 2][m] = v.z; AsT[c + 3][m] = v.w;
        }
#pragma unroll
        for (int l = tid; l < 512; l += 256) {
            int n = l >> 3, c = (l & 7) * 4;
            float4 v = *(const float4*)&Wp[(size_t)(n0 + n) * Cc + k0 + c];
            BsT[c + 0][n] = v.x; BsT[c + 1][n] = v.y;
            BsT[c + 2][n] = v.z; BsT[c + 3][n] = v.w;
        }
        __syncthreads();
#pragma unroll
        for (int kk = 0; kk < 32; kk++) {
            float4 av = *(const float4*)&AsT[kk][4 * ty];
            ull aB[4] = {pack2(av.x, av.x), pack2(av.y, av.y),
                         pack2(av.z, av.z), pack2(av.w, av.w)};
            ulonglong2 bb0 = *(const ulonglong2*)&BsT[kk][8 * tx];
            ulonglong2 bb1 = *(const ulonglong2*)&BsT[kk][8 * tx + 4];
            ull b2[4] = {bb0.x, bb0.y, bb1.x, bb1.y};
#pragma unroll
            for (int i = 0; i < 4; i++)
#pragma unroll
                for (int j = 0; j < 4; j++) ffma2(acc2[i][j], aB[i], b2[j]);
        }
        __syncthreads();
    }
#pragma unroll
    for (int i = 0; i < 4; i++) {
        int m = m0 + 4 * ty + i;
        float o[8];
#pragma unroll
        for (int j = 0; j < 4; j++) {
            float2 u = unpack2(acc2[i][j]);
            int n = n0 + 8 * tx + 2 * j;
            o[2 * j] = u.x + bp[n]; o[2 * j + 1] = u.y + bp[n + 1];
        }
        float* dst = &out[(size_t)m * Cc + n0 + 8 * tx];
        *(float4*)dst = make_float4(o[0], o[1], o[2], o[3]);
        *(float4*)(dst + 4) = make_float4(o[4], o[5], o[6], o[7]);
    }
}

// ---------------------------------------------------------------------------
extern "C" void kernel_launch(void* const* d_in, const int* in_sizes, int n_in,
                              void* d_out, int out_size) {
    (void)in_sizes; (void)n_in; (void)out_size;
    const float* q   = (const float*)d_in[0];
    const float* k_v = (const float*)d_in[1];
    const float* Wq  = (const float*)d_in[2];
    const float* Wk  = (const float*)d_in[3];
    const float* Wv  = (const float*)d_in[4];
    const float* Wp  = (const float*)d_in[5];
    const float* bp  = (const float*)d_in[6];
    float* out = (float*)d_out;

    dim3 gproj(Cc / 64, (Bb * Nn) / 128);              // (8, 32)
    proj_kernel<<<gproj, 256>>>(q,   Wq, 0);
    proj_kernel<<<gproj, 256>>>(k_v, Wk, 1);
    proj_kernel<<<gproj, 256>>>(k_v, Wv, 2);

    dim3 gqk(Nn / 64, Nn / 128, BH);                   // (32, 16, 16)
    qk_kernel<<<gqk, 256>>>();

    dim3 gsel(BH * Nn, 2);
    select_kernel<<<gsel, 256>>>();

    dim3 gspv(Nn / 128, BH);                           // (16, 16)
    spv_kernel<<<gspv, 256>>>();

    dim3 gout(Cc / 64, (Bb * Nn) / 128);
    outproj_kernel<<<gout, 256>>>(Wp, bp, out);
}

// round 4
// speedup vs baseline: 1.2522x; 1.2522x over previous
#include <cuda_runtime.h>
#include <cstdint>

#define Bb   2
#define Nn   2048
#define Cc   512
#define Hh   8
#define HD   64
#define BH   16
#define KTOP 1024
#define SCALEF 0.125f

// ---------------- scratch ----------------
__device__ float g_Qh[BH * Nn * HD];
__device__ float g_Kh[BH * Nn * HD];
__device__ float g_Vh[BH * Nn * HD];
__device__ float g_attn[(size_t)BH * Nn * Nn];
__device__ float g_attnT[(size_t)BH * Nn * Nn];
__device__ float g_rth[BH * Nn];
__device__ float g_cth[BH * Nn];
__device__ float g_rmax[BH * Nn];
__device__ float g_O[BH * Nn * HD];

// ---------------- tf32 helpers ----------------
__device__ __forceinline__ unsigned tf32_rna(float x) {
    unsigned u; asm("cvt.rna.tf32.f32 %0, %1;" : "=r"(u) : "f"(x)); return u;
}
__device__ __forceinline__ void split_tf32(float x, unsigned& hi, unsigned& lo) {
    hi = tf32_rna(x);
    float hf = __uint_as_float(hi);
    lo = tf32_rna(x - hf);
}
__device__ __forceinline__ void mma_tf32(float* c, const unsigned* a, const unsigned* b) {
    asm("mma.sync.aligned.m16n8k8.row.col.f32.tf32.tf32.f32 "
        "{%0,%1,%2,%3},{%4,%5,%6,%7},{%8,%9},{%0,%1,%2,%3};"
        : "+f"(c[0]), "+f"(c[1]), "+f"(c[2]), "+f"(c[3])
        : "r"(a[0]), "r"(a[1]), "r"(a[2]), "r"(a[3]), "r"(b[0]), "r"(b[1]));
}

// ---------------------------------------------------------------------------
// Kernel 1: projections  out = X @ W^T  scattered to [B,H,N,HD]   (R2 proven)
// ---------------------------------------------------------------------------
__global__ __launch_bounds__(128) void proj_kernel(const float* __restrict__ X,
                                                   const float* __restrict__ W,
                                                   int which) {
    __shared__ float As[128][33];
    __shared__ float Bs[64][33];
    int tid = threadIdx.x;
    int tx = tid & 7, ty = tid >> 3;
    int m0 = blockIdx.y * 128, n0 = blockIdx.x * 64;
    float acc[8][8] = {};
    for (int k0 = 0; k0 < Cc; k0 += 32) {
#pragma unroll
        for (int l = tid; l < 1024; l += 128) {
            int m = l >> 3, c = (l & 7) * 4;
            float4 v = *(const float4*)&X[(size_t)(m0 + m) * Cc + k0 + c];
            As[m][c] = v.x; As[m][c + 1] = v.y; As[m][c + 2] = v.z; As[m][c + 3] = v.w;
        }
#pragma unroll
        for (int l = tid; l < 512; l += 128) {
            int n = l >> 3, c = (l & 7) * 4;
            float4 v = *(const float4*)&W[(size_t)(n0 + n) * Cc + k0 + c];
            Bs[n][c] = v.x; Bs[n][c + 1] = v.y; Bs[n][c + 2] = v.z; Bs[n][c + 3] = v.w;
        }
        __syncthreads();
#pragma unroll
        for (int kk = 0; kk < 32; kk++) {
            float a[8], b[8];
#pragma unroll
            for (int i = 0; i < 8; i++) a[i] = As[8 * ty + i][kk];
#pragma unroll
            for (int j = 0; j < 8; j++) b[j] = Bs[8 * tx + j][kk];
#pragma unroll
            for (int i = 0; i < 8; i++)
#pragma unroll
                for (int j = 0; j < 8; j++) acc[i][j] += a[i] * b[j];
        }
        __syncthreads();
    }
    float* out = (which == 0) ? g_Qh : ((which == 1) ? g_Kh : g_Vh);
#pragma unroll
    for (int i = 0; i < 8; i++) {
        int m = m0 + 8 * ty + i;
        int bb = m >> 11, nl = m & (Nn - 1);
#pragma unroll
        for (int j = 0; j < 8; j++) {
            int n = n0 + 8 * tx + j;
            int h = n >> 6, d = n & 63;
            out[(((size_t)(bb * Hh + h)) * Nn + nl) * HD + d] = acc[i][j];
        }
    }
}

// ---------------------------------------------------------------------------
// Kernel 2 (NEW): attn = scale * Q K^T via 3xTF32 mma.sync, + transposed copy.
// Block 256 thr, tile M=128 x N=32, K=64 resident.
// Warps: wm = wid&3 (32 rows), wn = wid>>2 (16 cols); warp tile 32x16.
// smem: Qs[128][68] + Ks[32][68] = 43.5KB; Ts[128][36] overlays Qs.
// ---------------------------------------------------------------------------
__global__ __launch_bounds__(256) void qk_tc_kernel() {
    __shared__ float Qs[128][68];
    __shared__ float Ks[32][68];
    float (*Ts)[36] = (float(*)[36])Qs;     // epilogue staging (after sync)

    int tid = threadIdx.x;
    int wid = tid >> 5, lane = tid & 31;
    int g = lane >> 2, t = lane & 3;
    int wm = wid & 3, wn = wid >> 2;
    int bh = blockIdx.z;
    int i0 = blockIdx.y * 128, j0 = blockIdx.x * 32;
    const float* Q = g_Qh + (size_t)bh * Nn * HD;
    const float* K = g_Kh + (size_t)bh * Nn * HD;

    // load Q tile 128x64 (8 float4/thread), K tile 32x64 (2 float4/thread)
#pragma unroll
    for (int p = 0; p < 8; p++) {
        int idx = p * 256 + tid;
        int m = idx >> 4, c = (idx & 15) * 4;
        float4 v = *(const float4*)&Q[(size_t)(i0 + m) * HD + c];
        *(float4*)&Qs[m][c] = v;
    }
#pragma unroll
    for (int p = 0; p < 2; p++) {
        int idx = p * 256 + tid;
        int n = idx >> 4, c = (idx & 15) * 4;
        float4 v = *(const float4*)&K[(size_t)(j0 + n) * HD + c];
        *(float4*)&Ks[n][c] = v;
    }
    __syncthreads();

    float acc[2][2][4] = {};
#pragma unroll
    for (int ks = 0; ks < 8; ks++) {
        int k0 = ks * 8;
        unsigned ahi[2][4], alo[2][4], bhi[2][2], blo[2][2];
#pragma unroll
        for (int mt = 0; mt < 2; mt++) {
            int rb = 32 * wm + 16 * mt;
            float x0 = Qs[rb + g][k0 + t];
            float x1 = Qs[rb + g + 8][k0 + t];
            float x2 = Qs[rb + g][k0 + t + 4];
            float x3 = Qs[rb + g + 8][k0 + t + 4];
            split_tf32(x0, ahi[mt][0], alo[mt][0]);
            split_tf32(x1, ahi[mt][1], alo[mt][1]);
            split_tf32(x2, ahi[mt][2], alo[mt][2]);
            split_tf32(x3, ahi[mt][3], alo[mt][3]);
        }
#pragma unroll
        for (int nt = 0; nt < 2; nt++) {
            int nb = 16 * wn + 8 * nt;
            float y0 = Ks[nb + g][k0 + t];
            float y1 = Ks[nb + g][k0 + t + 4];
            split_tf32(y0, bhi[nt][0], blo[nt][0]);
            split_tf32(y1, bhi[nt][1], blo[nt][1]);
        }
#pragma unroll
        for (int mt = 0; mt < 2; mt++)
#pragma unroll
            for (int nt = 0; nt < 2; nt++) {
                mma_tf32(acc[mt][nt], ahi[mt], blo[nt]);
                mma_tf32(acc[mt][nt], alo[mt], bhi[nt]);
                mma_tf32(acc[mt][nt], ahi[mt], bhi[nt]);
            }
    }
    __syncthreads();                 // all fragment reads done; Ts overlays Qs

    // stage scaled result
#pragma unroll
    for (int mt = 0; mt < 2; mt++)
#pragma unroll
        for (int nt = 0; nt < 2; nt++) {
            int r0 = 32 * wm + 16 * mt + g;
            int c0 = 16 * wn + 8 * nt + 2 * t;
            Ts[r0][c0]         = acc[mt][nt][0] * SCALEF;
            Ts[r0][c0 + 1]     = acc[mt][nt][1] * SCALEF;
            Ts[r0 + 8][c0]     = acc[mt][nt][2] * SCALEF;
            Ts[r0 + 8][c0 + 1] = acc[mt][nt][3] * SCALEF;
        }
    __syncthreads();

    // attn: 128 rows x 32 cols, float4 coalesced
    float* attn = g_attn + ((size_t)bh * Nn + i0) * Nn + j0;
#pragma unroll
    for (int p = 0; p < 4; p++) {
        int idx = p * 256 + tid;
        int r = idx >> 3, cq = (idx & 7) * 4;
        *(float4*)&attn[(size_t)r * Nn + cq] = *(const float4*)&Ts[r][cq];
    }
    // attnT: 32 rows x 128 cols
    float* attnT = g_attnT + ((size_t)bh * Nn + j0) * Nn + i0;
#pragma unroll
    for (int p = 0; p < 16; p++) {
        int idx = p * 256 + tid;
        int jl = idx >> 7, il = idx & 127;
        attnT[(size_t)jl * Nn + il] = Ts[il][jl];
    }
}

// ---------------------------------------------------------------------------
// Kernel 3: exact K_TOP-th largest per row (radix select)   (R2 proven)
// ---------------------------------------------------------------------------
__global__ __launch_bounds__(256) void select_kernel() {
    __shared__ unsigned hist[4][256];
    __shared__ unsigned S[257];
    __shared__ unsigned s_sel, s_maxu;
    int tid = threadIdx.x;
    size_t row = blockIdx.x;
    int dir = blockIdx.y;
    const float* src = (dir ? g_attnT : g_attn) + row * Nn;

    unsigned u[8], lmax = 0u;
#pragma unroll
    for (int r = 0; r < 8; r++) {
        unsigned b = __float_as_uint(src[tid + 256 * r]);
        u[r] = b ^ ((unsigned)((int)b >> 31) | 0x80000000u);
        lmax = lmax > u[r] ? lmax : u[r];
    }
    if (tid == 0) s_maxu = 0u;

    unsigned prefix = 0u;
    int krem = KTOP;
    int hb = tid >> 6;
#pragma unroll
    for (int pass = 0; pass < 4; pass++) {
        int shift = 24 - 8 * pass;
        hist[0][tid] = 0u; hist[1][tid] = 0u; hist[2][tid] = 0u; hist[3][tid] = 0u;
        __syncthreads();
        if (pass == 0) atomicMax(&s_maxu, lmax);
        unsigned himask = (pass == 0) ? 0u : (0xFFFFFFFFu << (shift + 8));
#pragma unroll
        for (int r = 0; r < 8; r++)
            if ((u[r] & himask) == prefix)
                atomicAdd(&hist[hb][(u[r] >> shift) & 255u], 1u);
        __syncthreads();
        unsigned h = hist[0][tid] + hist[1][tid] + hist[2][tid] + hist[3][tid];
        hist[0][tid] = h;
        __syncthreads();
        if (tid < 32) {
            int base = tid * 8;
            unsigned c[8], loc[8];
#pragma unroll
            for (int j = 0; j < 8; j++) c[j] = hist[0][base + j];
            loc[7] = c[7];
#pragma unroll
            for (int j = 6; j >= 0; j--) loc[j] = c[j] + loc[j + 1];
            unsigned T = loc[0], incl = T;
#pragma unroll
            for (int off = 1; off < 32; off <<= 1) {
                unsigned v = __shfl_down_sync(0xFFFFFFFFu, incl, off);
                if (tid + off < 32) incl += v;
            }
            unsigned excl = incl - T;
#pragma unroll
            for (int j = 0; j < 8; j++) S[base + j] = excl + loc[j];
            if (tid == 0) S[256] = 0u;
        }
        __syncthreads();
        unsigned St = S[tid], St1 = S[tid + 1];
        if ((int)St >= krem && (int)St1 < krem) s_sel = (unsigned)tid;
        __syncthreads();
        unsigned sel = s_sel;
        krem -= (int)S[sel + 1];
        prefix |= sel << shift;
        __syncthreads();
    }
    if (tid == 0) {
        unsigned b = (prefix & 0x80000000u) ? (prefix ^ 0x80000000u) : ~prefix;
        float thr = __uint_as_float(b);
        if (dir) {
            g_cth[row] = thr;
        } else {
            g_rth[row] = thr;
            unsigned um = s_maxu;
            unsigned bm = (um & 0x80000000u) ? (um ^ 0x80000000u) : ~um;
            g_rmax[row] = __uint_as_float(bm);
        }
    }
}

// ---------------------------------------------------------------------------
// Kernel 4: fused masked softmax + P@V   (R2 proven)
// ---------------------------------------------------------------------------
__global__ __launch_bounds__(128) void spv_kernel() {
    __shared__ float Ps[128][33];
    __shared__ float Vs[32][68];
    __shared__ float s_rth[128], s_mx[128], s_cth[32], s_den[128];
    int tid = threadIdx.x;
    int tx = tid & 7, ty = tid >> 3;
    int bh = blockIdx.y;
    int i0 = blockIdx.x * 128;
    const float* V = g_Vh + (size_t)bh * Nn * HD;
    const float* A = g_attn + ((size_t)bh * Nn + i0) * Nn;
    s_rth[tid] = g_rth[bh * Nn + i0 + tid];
    s_mx[tid]  = g_rmax[bh * Nn + i0 + tid];
    s_den[tid] = 0.f;
    __syncthreads();
    float rthr[8], mr[8], dloc[8];
#pragma unroll
    for (int i = 0; i < 8; i++) {
        rthr[i] = s_rth[8 * ty + i];
        mr[i]   = s_mx[8 * ty + i];
        dloc[i] = 0.f;
    }
    float acc[8][8] = {};

    for (int j0 = 0; j0 < Nn; j0 += 32) {
        float4 araw[8];
#pragma unroll
        for (int i = 0; i < 8; i++)
            araw[i] = *(const float4*)&A[(size_t)(8 * ty + i) * Nn + j0 + 4 * tx];
        __syncthreads();
        if (tid < 32) s_cth[tid] = g_cth[bh * Nn + j0 + tid];
#pragma unroll
        for (int l = tid; l < 512; l += 128) {
            int jl = l >> 4, d = (l & 15) * 4;
            *(float4*)&Vs[jl][d] = *(const float4*)&V[(size_t)(j0 + jl) * HD + d];
        }
        __syncthreads();
#pragma unroll
        for (int i = 0; i < 8; i++) {
            float av[4] = {araw[i].x, araw[i].y, araw[i].z, araw[i].w};
#pragma unroll
            for (int uu = 0; uu < 4; uu++) {
                float a = av[uu];
                float thr = fminf(rthr[i], s_cth[4 * tx + uu]);
                float p = (a >= thr) ? __expf(a - mr[i]) : 0.f;
                dloc[i] += p;
                Ps[8 * ty + i][4 * tx + uu] = p;
            }
        }
        __syncthreads();
#pragma unroll
        for (int kk = 0; kk < 32; kk++) {
            float a[8], b[8];
#pragma unroll
            for (int i = 0; i < 8; i++) a[i] = Ps[8 * ty + i][kk];
            float4 b0 = *(const float4*)&Vs[kk][8 * tx];
            float4 b1 = *(const float4*)&Vs[kk][8 * tx + 4];
            b[0] = b0.x; b[1] = b0.y; b[2] = b0.z; b[3] = b0.w;
            b[4] = b1.x; b[5] = b1.y; b[6] = b1.z; b[7] = b1.w;
#pragma unroll
            for (int i = 0; i < 8; i++)
#pragma unroll
                for (int j = 0; j < 8; j++) acc[i][j] += a[i] * b[j];
        }
    }
#pragma unroll
    for (int i = 0; i < 8; i++) atomicAdd(&s_den[8 * ty + i], dloc[i]);
    __syncthreads();
#pragma unroll
    for (int i = 0; i < 8; i++) {
        int il = 8 * ty + i;
        float inv = 1.f / s_den[il];
        float4 v0 = make_float4(acc[i][0] * inv, acc[i][1] * inv, acc[i][2] * inv, acc[i][3] * inv);
        float4 v1 = make_float4(acc[i][4] * inv, acc[i][5] * inv, acc[i][6] * inv, acc[i][7] * inv);
        float* o = &g_O[((size_t)bh * Nn + i0 + il) * HD + 8 * tx];
        *(float4*)o = v0;
        *(float4*)(o + 4) = v1;
    }
}

// ---------------------------------------------------------------------------
// Kernel 5: output projection   (R2 proven)
// ---------------------------------------------------------------------------
__global__ __launch_bounds__(128) void outproj_kernel(const float* __restrict__ Wp,
                                                      const float* __restrict__ bp,
                                                      float* __restrict__ out) {
    __shared__ float As[128][33];
    __shared__ float Bs[64][33];
    int tid = threadIdx.x;
    int tx = tid & 7, ty = tid >> 3;
    int m0 = blockIdx.y * 128, n0 = blockIdx.x * 64;
    float acc[8][8] = {};
    for (int k0 = 0; k0 < Cc; k0 += 32) {
        int h = k0 >> 6;
#pragma unroll
        for (int l = tid; l < 1024; l += 128) {
            int m = l >> 3, c = (l & 7) * 4;
            int mg = m0 + m;
            int bb = mg >> 11, nl = mg & (Nn - 1);
            int d = (k0 + c) & 63;
            float4 v = *(const float4*)&g_O[(((size_t)(bb * Hh + h)) * Nn + nl) * HD + d];
            As[m][c] = v.x; As[m][c + 1] = v.y; As[m][c + 2] = v.z; As[m][c + 3] = v.w;
        }
#pragma unroll
        for (int l = tid; l < 512; l += 128) {
            int n = l >> 3, c = (l & 7) * 4;
            float4 v = *(const float4*)&Wp[(size_t)(n0 + n) * Cc + k0 + c];
            Bs[n][c] = v.x; Bs[n][c + 1] = v.y; Bs[n][c + 2] = v.z; Bs[n][c + 3] = v.w;
        }
        __syncthreads();
#pragma unroll
        for (int kk = 0; kk < 32; kk++) {
            float a[8], b[8];
#pragma unroll
            for (int i = 0; i < 8; i++) a[i] = As[8 * ty + i][kk];
#pragma unroll
            for (int j = 0; j < 8; j++) b[j] = Bs[8 * tx + j][kk];
#pragma unroll
            for (int i = 0; i < 8; i++)
#pragma unroll
                for (int j = 0; j < 8; j++) acc[i][j] += a[i] * b[j];
        }
        __syncthreads();
    }
#pragma unroll
    for (int i = 0; i < 8; i++) {
        int m = m0 + 8 * ty + i;
#pragma unroll
        for (int j = 0; j < 8; j++) {
            int n = n0 + 8 * tx + j;
            out[(size_t)m * Cc + n] = acc[i][j] + bp[n];
        }
    }
}

// ---------------------------------------------------------------------------
extern "C" void kernel_launch(void* const* d_in, const int* in_sizes, int n_in,
                              void* d_out, int out_size) {
    (void)in_sizes; (void)n_in; (void)out_size;
    const float* q   = (const float*)d_in[0];
    const float* k_v = (const float*)d_in[1];
    const float* Wq  = (const float*)d_in[2];
    const float* Wk  = (const float*)d_in[3];
    const float* Wv  = (const float*)d_in[4];
    const float* Wp  = (const float*)d_in[5];
    const float* bp  = (const float*)d_in[6];
    float* out = (float*)d_out;

    dim3 gproj(Cc / 64, (Bb * Nn) / 128);              // (8, 32)
    proj_kernel<<<gproj, 128>>>(q,   Wq, 0);
    proj_kernel<<<gproj, 128>>>(k_v, Wk, 1);
    proj_kernel<<<gproj, 128>>>(k_v, Wv, 2);

    dim3 gqk(Nn / 32, Nn / 128, BH);                   // (64, 16, 16)
    qk_tc_kernel<<<gqk, 256>>>();

    dim3 gsel(BH * Nn, 2);
    select_kernel<<<gsel, 256>>>();

    dim3 gspv(Nn / 128, BH);                           // (16, 16)
    spv_kernel<<<gspv, 128>>>();

    dim3 gout(Cc / 64, (Bb * Nn) / 128);
    outproj_kernel<<<gout, 128>>>(Wp, bp, out);
}